// round 13
// baseline (speedup 1.0000x reference)
#include <cuda_runtime.h>
#include <cuda_fp16.h>
#include <cstdint>

// Problem constants
#define BB 2
#define NN 2048
#define DD 1024
#define HH 16
#define DH 64
#define MTOT (BB * NN)          // 4096
#define CE2 (0.0450842350f)     // (1/32) * log2(e), folded into Wq

// ---------------------------------------------------------------------------
// Scratch (device globals; allocation is forbidden)
// ---------------------------------------------------------------------------
__device__ __half g_xe[MTOT * DD];
__device__ __half g_Qe[MTOT * DD];      // pre-scaled by CE2 (via Wq)
__device__ __half g_Ke[MTOT * DD];
__device__ __half g_Ve[MTOT * DD];
__device__ __half g_Ce[MTOT * DD];

__device__ __half g_Wqt[DD * DD];
__device__ __half g_Wkt[DD * DD];
__device__ __half g_Wvt[DD * DD];
__device__ __half g_Wot[DD * DD];

// ---------------------------------------------------------------------------
// PTX helpers
// ---------------------------------------------------------------------------
__device__ __forceinline__ uint32_t smem_to_u32(const void* p) {
    uint32_t a;
    asm("{ .reg .u64 t; cvta.to.shared.u64 t, %1; cvt.u32.u64 %0, t; }" : "=r"(a) : "l"(p));
    return a;
}
#define CP_ASYNC16(dst, src) \
    asm volatile("cp.async.cg.shared.global [%0], [%1], 16;" :: "r"(dst), "l"(src))
#define CP_COMMIT() asm volatile("cp.async.commit_group;")
#define CP_WAIT(n)  asm volatile("cp.async.wait_group %0;" :: "n"(n))

#define LDSM4(r, addr) \
    asm volatile("ldmatrix.sync.aligned.m8n8.x4.shared.b16 {%0,%1,%2,%3}, [%4];" \
        : "=r"((r)[0]), "=r"((r)[1]), "=r"((r)[2]), "=r"((r)[3]) : "r"(addr))
#define LDSM4T(r, addr) \
    asm volatile("ldmatrix.sync.aligned.m8n8.x4.trans.shared.b16 {%0,%1,%2,%3}, [%4];" \
        : "=r"((r)[0]), "=r"((r)[1]), "=r"((r)[2]), "=r"((r)[3]) : "r"(addr))

#define MMAF16(d, a, b0, b1) \
    asm volatile("mma.sync.aligned.m16n8k16.row.col.f32.f16.f16.f32 " \
        "{%0,%1,%2,%3}, {%4,%5,%6,%7}, {%8,%9}, {%0,%1,%2,%3};" \
        : "+f"((d)[0]), "+f"((d)[1]), "+f"((d)[2]), "+f"((d)[3]) \
        : "r"((a)[0]), "r"((a)[1]), "r"((a)[2]), "r"((a)[3]), "r"(b0), "r"(b1))

__device__ __forceinline__ uint32_t pack_f16x2(float a0, float a1) {
    uint32_t d;
    asm("cvt.rn.f16x2.f32 %0, %1, %2;" : "=r"(d) : "f"(a1), "f"(a0));
    return d;
}
__device__ __forceinline__ uint32_t h2ex2(uint32_t x) {
    uint32_t r;
    asm("ex2.approx.f16x2 %0, %1;" : "=r"(r) : "r"(x));
    return r;
}
#define ONES2 0x3C003C00u        // fp16x2 {1.0, 1.0}

// XOR-swizzled smem offset: row r (128B rows), 16B chunk c (0..7)
#define SW_OFF(r, c) ((uint32_t)(r) * 128 + ((((c) ^ ((r) & 7))) << 4))

// ---------------------------------------------------------------------------
// fp32 -> fp16 convert, vectorized
// ---------------------------------------------------------------------------
__global__ __launch_bounds__(256) void conv_kernel(
    const float* __restrict__ a, __half* __restrict__ o)
{
    const int i = blockIdx.x * 256 + threadIdx.x;
    float4 v = ((const float4*)a)[i];
    ((__half2*)o)[2 * i + 0] = __half2(__float2half_rn(v.x), __float2half_rn(v.y));
    ((__half2*)o)[2 * i + 1] = __half2(__float2half_rn(v.z), __float2half_rn(v.w));
}

// ---------------------------------------------------------------------------
// Fused: 4x  W [K][N] fp32 -> transposed fp16 Wt [N][K], with per-z scale
// ---------------------------------------------------------------------------
struct TransArgs { const float* W[4]; __half* Wt[4]; float scale[4]; };

__global__ __launch_bounds__(256) void transT_all(TransArgs args)
{
    __shared__ float t[32][33];
    const float* __restrict__ W = args.W[blockIdx.z];
    __half* __restrict__ Wt = args.Wt[blockIdx.z];
    const float s = args.scale[blockIdx.z];
    const int bx = blockIdx.x * 32;
    const int by = blockIdx.y * 32;
    const int tx = threadIdx.x, ty0 = threadIdx.y;
    #pragma unroll
    for (int i = 0; i < 4; i++) {
        const int ty = ty0 + i * 8;
        t[ty][tx] = W[(by + ty) * DD + bx + tx];
    }
    __syncthreads();
    #pragma unroll
    for (int i = 0; i < 4; i++) {
        const int ty = ty0 + i * 8;
        Wt[(size_t)(bx + ty) * DD + by + tx] = __float2half_rn(t[tx][ty] * s);
    }
}

// ---------------------------------------------------------------------------
// Single-product fp16 GEMM mainloop, XOR-swizzled smem, double buffer with
// ONE sync per chunk (wait -> sync -> issue next loads -> compute; the top
// sync both publishes the finished group and proves all warps are done
// reading the buffer the new loads overwrite).
// ---------------------------------------------------------------------------
#define MAT_BYTES (128 * 128)        // 16384
#define STG1 (2 * MAT_BYTES)         // 32768
#define G1SMEM (2 * STG1)            // 65536

#define LOADS1(chunk, buf, A, B) do { \
    const int k0 = (chunk) * 64; \
    const uint32_t s0 = sb + (buf) * STG1; \
    _Pragma("unroll") \
    for (int i = 0; i < 8; i++) { \
        const int idx = tid + i * 256; \
        const int mat = idx >> 10; \
        const int r = (idx >> 3) & 127; \
        const int c = idx & 7; \
        const size_t g = (size_t)((mat ? col0 : row0) + r) * DD + k0 + c * 8; \
        CP_ASYNC16(s0 + mat * MAT_BYTES + SW_OFF(r, c), (mat ? (B) : (A)) + g); \
    } \
} while (0)

#define GEMM_MAINLOOP(A, B, acc) \
    const uint32_t sb = smem_to_u32(smem); \
    const int tid = threadIdx.x; \
    const int row0 = blockIdx.y * 128; \
    const int col0 = blockIdx.x * 128; \
    const int wid = tid >> 5; \
    const int lane = tid & 31; \
    const int mrow = (wid & 3) * 32; \
    const int ncol = (wid >> 2) * 64; \
    const int lm = lane & 15; \
    const int hc = (lane >> 4) & 1; \
    _Pragma("unroll") \
    for (int i = 0; i < 2; i++) \
        _Pragma("unroll") \
        for (int j = 0; j < 8; j++) \
            _Pragma("unroll") \
            for (int k = 0; k < 4; k++) acc[i][j][k] = 0.f; \
    LOADS1(0, 0, A, B); \
    CP_COMMIT(); \
    const int KC = DD / 64; \
    for (int c = 0; c < KC; c++) { \
        const int buf = c & 1; \
        CP_WAIT(0); \
        __syncthreads(); \
        if (c + 1 < KC) { LOADS1(c + 1, buf ^ 1, A, B); CP_COMMIT(); } \
        const uint32_t sA = sb + buf * STG1; \
        const uint32_t sB = sA + MAT_BYTES; \
        _Pragma("unroll") \
        for (int ks = 0; ks < 4; ks++) { \
            const int ch = ks * 2 + hc; \
            uint32_t af[2][4], bf[4][4]; \
            _Pragma("unroll") \
            for (int mt = 0; mt < 2; mt++) \
                LDSM4(af[mt], sA + SW_OFF(mrow + mt * 16 + lm, ch)); \
            _Pragma("unroll") \
            for (int nt = 0; nt < 4; nt++) \
                LDSM4(bf[nt], sB + SW_OFF(ncol + nt * 16 + lm, ch)); \
            _Pragma("unroll") \
            for (int mt = 0; mt < 2; mt++) \
                _Pragma("unroll") \
                for (int nt = 0; nt < 4; nt++) { \
                    MMAF16(acc[mt][2 * nt + 0], af[mt], bf[nt][0], bf[nt][2]); \
                    MMAF16(acc[mt][2 * nt + 1], af[mt], bf[nt][1], bf[nt][3]); \
                } \
        } \
    }

struct Gemm1Args { const __half* B[3]; __half* O[3]; };

// QKV: fp16 out
__global__ __launch_bounds__(256) void gemm_1p(
    const __half* __restrict__ A, Gemm1Args args)
{
    extern __shared__ __align__(128) char smem[];
    const int z = blockIdx.z;
    const __half* __restrict__ B = args.B[z];
    float acc[2][8][4];
    GEMM_MAINLOOP(A, B, acc)

    const int quad = lane >> 2;
    const int qt = lane & 3;
    __half* O = args.O[z];
    #pragma unroll
    for (int mt = 0; mt < 2; mt++) {
        const int r_lo = row0 + mrow + mt * 16 + quad;
        #pragma unroll
        for (int nt = 0; nt < 8; nt++) {
            const int col = col0 + ncol + nt * 8 + 2 * qt;
            #pragma unroll
            for (int half = 0; half < 2; half++) {
                const size_t o = (size_t)(r_lo + 8 * half) * DD + col;
                *(uint32_t*)&O[o] =
                    pack_f16x2(acc[mt][nt][2 * half], acc[mt][nt][2 * half + 1]);
            }
        }
    }
}

// O-proj: f32 out + bias
__global__ __launch_bounds__(256) void gemm_1pf(
    const __half* __restrict__ A, const __half* __restrict__ Bw,
    const float* __restrict__ bias, float* __restrict__ C)
{
    extern __shared__ __align__(128) char smem[];
    const __half* __restrict__ B = Bw;
    float acc[2][8][4];
    GEMM_MAINLOOP(A, B, acc)

    const int quad = lane >> 2;
    const int qt = lane & 3;
    #pragma unroll
    for (int mt = 0; mt < 2; mt++) {
        const int r_lo = row0 + mrow + mt * 16 + quad;
        #pragma unroll
        for (int nt = 0; nt < 8; nt++) {
            const int col = col0 + ncol + nt * 8 + 2 * qt;
            float2 v0 = make_float2(acc[mt][nt][0], acc[mt][nt][1]);
            float2 v1 = make_float2(acc[mt][nt][2], acc[mt][nt][3]);
            const float2 bv = *(const float2*)&bias[col];
            v0.x += bv.x; v0.y += bv.y;
            v1.x += bv.x; v1.y += bv.y;
            *(float2*)&C[(size_t)r_lo * DD + col] = v0;
            *(float2*)&C[(size_t)(r_lo + 8) * DD + col] = v1;
        }
    }
}

// ---------------------------------------------------------------------------
// Tensor-core causal flash attention, diagonal-paired (each CTA: q-tile 31-i
// then q-tile i -> exactly 33 KV tiles per CTA; grid 512 = one wave).
// Double-buffered KV with ONE sync per tile. 64 q rows (4 warps x 16),
// XOR swizzle, 4 CTAs/SM. Q pre-scaled by CE2; P = ex2.f16x2; ones-MMA sums.
// ---------------------------------------------------------------------------
#define AQ_BYTES (64 * 128)                  // 8192
#define AKV_MAT (64 * 128)                   // 8192
#define AKV_STG (2 * AKV_MAT)                // 16384
#define ASMEM_BYTES (AQ_BYTES + 2 * AKV_STG) // 40960
#define NQT (NN / 64)                        // 32 q-tiles per (b,h)

__global__ __launch_bounds__(128, 4) void attn_tc(
    const __half* __restrict__ Qe, const __half* __restrict__ Ke,
    const __half* __restrict__ Ve, __half* __restrict__ Ce)
{
    extern __shared__ __align__(128) char smem[];
    const uint32_t sb = smem_to_u32(smem);
    const int OFF_Q = 0, OFF_ST = AQ_BYTES;

    const int tid = threadIdx.x;
    const int wid = tid >> 5;
    const int lane = tid & 31;
    const int quad = lane >> 2;
    const int qt = lane & 3;
    const int lm = lane & 15;
    const int hc = (lane >> 4) & 1;

    const int pairi = blockIdx.x;     // 0..15
    const int h = blockIdx.y;
    const int b = blockIdx.z;
    const int hoff = h * DH;
    const int rowg = b * NN;

    #define LOADKV(kt, buf) do { \
        _Pragma("unroll") \
        for (int i = 0; i < 8; i++) { \
            const int idx = tid + i * 128; \
            const int mat = idx >> 9; \
            const int r = (idx >> 3) & 63; \
            const int c = idx & 7; \
            const uint32_t dst = sb + OFF_ST + (buf) * AKV_STG + mat * AKV_MAT \
                               + SW_OFF(r, c); \
            const size_t g = (size_t)(rowg + (kt) * 64 + r) * DD + hoff + c * 8; \
            CP_ASYNC16(dst, (mat ? Ve : Ke) + g); \
        } \
    } while (0)

    #pragma unroll 1
    for (int pass = 0; pass < 2; pass++) {
        const int qb = pass ? pairi : (NQT - 1 - pairi);
        const int q0 = qb * 64;

        // Prologue: Q tile + KV tile 0 as one group
        #pragma unroll
        for (int i = 0; i < 4; i++) {
            const int idx = tid + i * 128;
            const int r = idx >> 3, c = idx & 7;
            CP_ASYNC16(sb + OFF_Q + SW_OFF(r, c),
                       Qe + (size_t)(rowg + q0 + r) * DD + hoff + c * 8);
        }
        LOADKV(0, 0);
        CP_COMMIT();
        CP_WAIT(0);
        __syncthreads();

        uint32_t qf[4][4];
        #pragma unroll
        for (int kk = 0; kk < 4; kk++)
            LDSM4(qf[kk], sb + OFF_Q + SW_OFF(wid * 16 + lm, kk * 2 + hc));

        float ctx[8][4];
        #pragma unroll
        for (int j = 0; j < 8; j++)
            #pragma unroll
            for (int k = 0; k < 4; k++) ctx[j][k] = 0.f;
        float lacc[4] = {0.f, 0.f, 0.f, 0.f};

        const int rbase = q0 + wid * 16 + quad;
        const int wrow0 = q0 + wid * 16;
        const int nkt = qb + 1;

        for (int kt = 0; kt < nkt; kt++) {
            const int buf = kt & 1;
            if (kt > 0) {           // tile kt's group is the only pending one
                CP_WAIT(0);
                __syncthreads();    // publish loads + prove buf^1 free to rewrite
            }
            if (kt + 1 < nkt) {
                LOADKV(kt + 1, buf ^ 1);
                CP_COMMIT();
            }

            const uint32_t sK = sb + OFF_ST + buf * AKV_STG;
            const uint32_t sV = sK + AKV_MAT;

            // ---- S = Q @ K^T (log2 units) ----
            float sacc[8][4];
            #pragma unroll
            for (int j = 0; j < 8; j++)
                #pragma unroll
                for (int k = 0; k < 4; k++) sacc[j][k] = 0.f;

            #pragma unroll
            for (int kk = 0; kk < 4; kk++) {
                uint32_t kf[4][4];
                #pragma unroll
                for (int nt = 0; nt < 4; nt++)
                    LDSM4(kf[nt], sK + SW_OFF(nt * 16 + lm, kk * 2 + hc));
                #pragma unroll
                for (int nt = 0; nt < 4; nt++) {
                    MMAF16(sacc[2 * nt + 0], qf[kk], kf[nt][0], kf[nt][2]);
                    MMAF16(sacc[2 * nt + 1], qf[kk], kf[nt][1], kf[nt][3]);
                }
            }

            // ---- causal mask (diagonal tiles only) ----
            if ((kt + 1) * 64 > wrow0) {
                const int kcb = kt * 64 + 2 * qt;
                #pragma unroll
                for (int j = 0; j < 8; j++) {
                    const int c0 = kcb + j * 8;
                    if (c0     > rbase    ) sacc[j][0] = -60000.f;
                    if (c0 + 1 > rbase    ) sacc[j][1] = -60000.f;
                    if (c0     > rbase + 8) sacc[j][2] = -60000.f;
                    if (c0 + 1 > rbase + 8) sacc[j][3] = -60000.f;
                }
            }

            // ---- P = ex2(S) in fp16x2; row sums via ones-MMA ----
            uint32_t pf[4][4];
            #pragma unroll
            for (int t = 0; t < 4; t++) {
                #pragma unroll
                for (int g = 0; g < 4; g++) {
                    const int jj = 2 * t + (g >> 1);
                    const int o = (g & 1) * 2;
                    pf[t][g] = h2ex2(pack_f16x2(sacc[jj][o + 0], sacc[jj][o + 1]));
                }
            }
            #pragma unroll
            for (int t = 0; t < 4; t++)
                MMAF16(lacc, pf[t], ONES2, ONES2);

            // ---- ctx += P @ V ----
            #pragma unroll
            for (int t = 0; t < 4; t++) {
                #pragma unroll
                for (int jj = 0; jj < 4; jj++) {
                    uint32_t vf[4];
                    LDSM4T(vf, sV + SW_OFF(t * 16 + lm, jj * 2 + hc));
                    MMAF16(ctx[2 * jj + 0], pf[t], vf[0], vf[1]);
                    MMAF16(ctx[2 * jj + 1], pf[t], vf[2], vf[3]);
                }
            }
        }

        // ---- epilogue for this pass ----
        const float i0 = 1.f / lacc[0];
        const float i1 = 1.f / lacc[2];
        #pragma unroll
        for (int jj = 0; jj < 8; jj++) {
            const int col = hoff + jj * 8 + 2 * qt;
            #pragma unroll
            for (int half = 0; half < 2; half++) {
                const float inv = half ? i1 : i0;
                const size_t o = (size_t)(rowg + rbase + 8 * half) * DD + col;
                *(uint32_t*)&Ce[o] = pack_f16x2(ctx[jj][2 * half + 0] * inv,
                                                ctx[jj][2 * half + 1] * inv);
            }
        }
        __syncthreads();   // smem safe to reuse in next pass
    }
    #undef LOADKV
}

// ---------------------------------------------------------------------------
// Launch
// ---------------------------------------------------------------------------
extern "C" void kernel_launch(void* const* d_in, const int* in_sizes, int n_in,
                              void* d_out, int out_size)
{
    const float* x  = (const float*)d_in[0];
    const float* Wq = (const float*)d_in[1];
    const float* Wk = (const float*)d_in[2];
    const float* Wv = (const float*)d_in[3];
    const float* Wo = (const float*)d_in[4];
    const float* bo = (const float*)d_in[5];
    float* out = (float*)d_out;

    __half *xe, *Qe, *Ke, *Ve, *Ce;
    cudaGetSymbolAddress((void**)&xe, g_xe);
    cudaGetSymbolAddress((void**)&Qe, g_Qe);
    cudaGetSymbolAddress((void**)&Ke, g_Ke);
    cudaGetSymbolAddress((void**)&Ve, g_Ve);
    cudaGetSymbolAddress((void**)&Ce, g_Ce);
    __half *Wqt, *Wkt, *Wvt, *Wot;
    cudaGetSymbolAddress((void**)&Wqt, g_Wqt);
    cudaGetSymbolAddress((void**)&Wkt, g_Wkt);
    cudaGetSymbolAddress((void**)&Wvt, g_Wvt);
    cudaGetSymbolAddress((void**)&Wot, g_Wot);

    cudaFuncSetAttribute(gemm_1p, cudaFuncAttributeMaxDynamicSharedMemorySize, G1SMEM);
    cudaFuncSetAttribute(gemm_1pf, cudaFuncAttributeMaxDynamicSharedMemorySize, G1SMEM);
    cudaFuncSetAttribute(attn_tc, cudaFuncAttributeMaxDynamicSharedMemorySize, ASMEM_BYTES);

    // Prep
    conv_kernel<<<(MTOT * DD) / (4 * 256), 256>>>(x, xe);
    {
        TransArgs t;
        t.W[0] = Wq; t.Wt[0] = Wqt; t.scale[0] = CE2;
        t.W[1] = Wk; t.Wt[1] = Wkt; t.scale[1] = 1.f;
        t.W[2] = Wv; t.Wt[2] = Wvt; t.scale[2] = 1.f;
        t.W[3] = Wo; t.Wt[3] = Wot; t.scale[3] = 1.f;
        dim3 tb(32, 8), tg(DD / 32, DD / 32, 4);
        transT_all<<<tg, tb>>>(t);
    }

    // Fused QKV projections (single product)
    {
        Gemm1Args a;
        a.B[0] = Wqt; a.O[0] = Qe;
        a.B[1] = Wkt; a.O[1] = Ke;
        a.B[2] = Wvt; a.O[2] = Ve;
        dim3 gg(DD / 128, MTOT / 128, 3);
        gemm_1p<<<gg, 256, G1SMEM>>>(xe, a);
    }

    // Tensor-core attention: 512 CTAs, each = one heavy + one light q-tile
    {
        dim3 ga(NQT / 2, HH, BB);   // (16, 16, 2)
        attn_tc<<<ga, 128, ASMEM_BYTES>>>(Qe, Ke, Ve, Ce);
    }

    // Output projection (single product, f32 + bias)
    {
        dim3 gg(DD / 128, MTOT / 128);
        gemm_1pf<<<gg, 256, G1SMEM>>>(Ce, Wot, bo, out);
    }
}

// round 16
// speedup vs baseline: 1.0089x; 1.0089x over previous
#include <cuda_runtime.h>
#include <cuda_fp16.h>
#include <cstdint>

// Problem constants
#define BB 2
#define NN 2048
#define DD 1024
#define HH 16
#define DH 64
#define MTOT (BB * NN)          // 4096
#define CE2 (0.0450842350f)     // (1/32) * log2(e), folded into Wq

// ---------------------------------------------------------------------------
// Scratch (device globals; allocation is forbidden)
// ---------------------------------------------------------------------------
__device__ __half g_xe[MTOT * DD];
__device__ __half g_Qe[MTOT * DD];      // pre-scaled by CE2 (via Wq)
__device__ __half g_Ke[MTOT * DD];
__device__ __half g_Ve[MTOT * DD];
__device__ __half g_Ce[MTOT * DD];

__device__ __half g_Wqt[DD * DD];
__device__ __half g_Wkt[DD * DD];
__device__ __half g_Wvt[DD * DD];
__device__ __half g_Wot[DD * DD];

// ---------------------------------------------------------------------------
// PTX helpers
// ---------------------------------------------------------------------------
__device__ __forceinline__ uint32_t smem_to_u32(const void* p) {
    uint32_t a;
    asm("{ .reg .u64 t; cvta.to.shared.u64 t, %1; cvt.u32.u64 %0, t; }" : "=r"(a) : "l"(p));
    return a;
}
#define CP_ASYNC16(dst, src) \
    asm volatile("cp.async.cg.shared.global [%0], [%1], 16;" :: "r"(dst), "l"(src))
#define CP_COMMIT() asm volatile("cp.async.commit_group;")
#define CP_WAIT(n)  asm volatile("cp.async.wait_group %0;" :: "n"(n))

#define LDSM4(r, addr) \
    asm volatile("ldmatrix.sync.aligned.m8n8.x4.shared.b16 {%0,%1,%2,%3}, [%4];" \
        : "=r"((r)[0]), "=r"((r)[1]), "=r"((r)[2]), "=r"((r)[3]) : "r"(addr))
#define LDSM4T(r, addr) \
    asm volatile("ldmatrix.sync.aligned.m8n8.x4.trans.shared.b16 {%0,%1,%2,%3}, [%4];" \
        : "=r"((r)[0]), "=r"((r)[1]), "=r"((r)[2]), "=r"((r)[3]) : "r"(addr))

#define MMAF16(d, a, b0, b1) \
    asm volatile("mma.sync.aligned.m16n8k16.row.col.f32.f16.f16.f32 " \
        "{%0,%1,%2,%3}, {%4,%5,%6,%7}, {%8,%9}, {%0,%1,%2,%3};" \
        : "+f"((d)[0]), "+f"((d)[1]), "+f"((d)[2]), "+f"((d)[3]) \
        : "r"((a)[0]), "r"((a)[1]), "r"((a)[2]), "r"((a)[3]), "r"(b0), "r"(b1))

__device__ __forceinline__ uint32_t pack_f16x2(float a0, float a1) {
    uint32_t d;
    asm("cvt.rn.f16x2.f32 %0, %1, %2;" : "=r"(d) : "f"(a1), "f"(a0));
    return d;
}
__device__ __forceinline__ uint32_t h2ex2(uint32_t x) {
    uint32_t r;
    asm("ex2.approx.f16x2 %0, %1;" : "=r"(r) : "r"(x));
    return r;
}
#define ONES2 0x3C003C00u        // fp16x2 {1.0, 1.0}

// XOR-swizzled smem offset: row r (128B rows), 16B chunk c (0..7)
#define SW_OFF(r, c) ((uint32_t)(r) * 128 + ((((c) ^ ((r) & 7))) << 4))

// ---------------------------------------------------------------------------
// Fused prep: z<4 -> W[z] [K][N] fp32 -> transposed fp16 Wt [N][K] (scaled);
//             z==4 -> x fp32 -> fp16 (1024 blocks cover 4M elements).
// Block = (32, 8) threads.
// ---------------------------------------------------------------------------
struct PrepArgs {
    const float* W[4]; __half* Wt[4]; float scale[4];
    const float* x; __half* xe;
};

__global__ __launch_bounds__(256) void prep_all(PrepArgs args)
{
    if (blockIdx.z == 4) {
        // x conversion: 1024 blocks * 256 thr * 4 float4 = 4M elems
        const int tidl = threadIdx.y * 32 + threadIdx.x;
        const int bid = blockIdx.y * gridDim.x + blockIdx.x;
        #pragma unroll
        for (int k = 0; k < 4; k++) {
            const int i = (bid * 4 + k) * 256 + tidl;
            float4 v = ((const float4*)args.x)[i];
            ((__half2*)args.xe)[2 * i + 0] = __half2(__float2half_rn(v.x), __float2half_rn(v.y));
            ((__half2*)args.xe)[2 * i + 1] = __half2(__float2half_rn(v.z), __float2half_rn(v.w));
        }
        return;
    }
    __shared__ float t[32][33];
    const float* __restrict__ W = args.W[blockIdx.z];
    __half* __restrict__ Wt = args.Wt[blockIdx.z];
    const float s = args.scale[blockIdx.z];
    const int bx = blockIdx.x * 32;
    const int by = blockIdx.y * 32;
    const int tx = threadIdx.x, ty0 = threadIdx.y;
    #pragma unroll
    for (int i = 0; i < 4; i++) {
        const int ty = ty0 + i * 8;
        t[ty][tx] = W[(by + ty) * DD + bx + tx];
    }
    __syncthreads();
    #pragma unroll
    for (int i = 0; i < 4; i++) {
        const int ty = ty0 + i * 8;
        Wt[(size_t)(bx + ty) * DD + by + tx] = __float2half_rn(t[tx][ty] * s);
    }
}

// ---------------------------------------------------------------------------
// Single-product fp16 GEMM mainloop, XOR-swizzled smem, double buffer,
// one sync per chunk.
// ---------------------------------------------------------------------------
#define MAT_BYTES (128 * 128)        // 16384
#define STG1 (2 * MAT_BYTES)         // 32768
#define G1SMEM (2 * STG1)            // 65536

#define LOADS1(chunk, buf, A, B) do { \
    const int k0 = (chunk) * 64; \
    const uint32_t s0 = sb + (buf) * STG1; \
    _Pragma("unroll") \
    for (int i = 0; i < 8; i++) { \
        const int idx = tid + i * 256; \
        const int mat = idx >> 10; \
        const int r = (idx >> 3) & 127; \
        const int c = idx & 7; \
        const size_t g = (size_t)((mat ? col0 : row0) + r) * DD + k0 + c * 8; \
        CP_ASYNC16(s0 + mat * MAT_BYTES + SW_OFF(r, c), (mat ? (B) : (A)) + g); \
    } \
} while (0)

#define GEMM_MAINLOOP(A, B, acc) \
    const uint32_t sb = smem_to_u32(smem); \
    const int tid = threadIdx.x; \
    const int row0 = blockIdx.y * 128; \
    const int col0 = blockIdx.x * 128; \
    const int wid = tid >> 5; \
    const int lane = tid & 31; \
    const int mrow = (wid & 3) * 32; \
    const int ncol = (wid >> 2) * 64; \
    const int lm = lane & 15; \
    const int hc = (lane >> 4) & 1; \
    _Pragma("unroll") \
    for (int i = 0; i < 2; i++) \
        _Pragma("unroll") \
        for (int j = 0; j < 8; j++) \
            _Pragma("unroll") \
            for (int k = 0; k < 4; k++) acc[i][j][k] = 0.f; \
    LOADS1(0, 0, A, B); \
    CP_COMMIT(); \
    const int KC = DD / 64; \
    for (int c = 0; c < KC; c++) { \
        const int buf = c & 1; \
        CP_WAIT(0); \
        __syncthreads(); \
        if (c + 1 < KC) { LOADS1(c + 1, buf ^ 1, A, B); CP_COMMIT(); } \
        const uint32_t sA = sb + buf * STG1; \
        const uint32_t sB = sA + MAT_BYTES; \
        _Pragma("unroll") \
        for (int ks = 0; ks < 4; ks++) { \
            const int ch = ks * 2 + hc; \
            uint32_t af[2][4], bf[4][4]; \
            _Pragma("unroll") \
            for (int mt = 0; mt < 2; mt++) \
                LDSM4(af[mt], sA + SW_OFF(mrow + mt * 16 + lm, ch)); \
            _Pragma("unroll") \
            for (int nt = 0; nt < 4; nt++) \
                LDSM4(bf[nt], sB + SW_OFF(ncol + nt * 16 + lm, ch)); \
            _Pragma("unroll") \
            for (int mt = 0; mt < 2; mt++) \
                _Pragma("unroll") \
                for (int nt = 0; nt < 4; nt++) { \
                    MMAF16(acc[mt][2 * nt + 0], af[mt], bf[nt][0], bf[nt][2]); \
                    MMAF16(acc[mt][2 * nt + 1], af[mt], bf[nt][1], bf[nt][3]); \
                } \
        } \
    }

struct Gemm1Args { const __half* B[3]; __half* O[3]; };

// QKV: fp16 out
__global__ __launch_bounds__(256) void gemm_1p(
    const __half* __restrict__ A, Gemm1Args args)
{
    extern __shared__ __align__(128) char smem[];
    const int z = blockIdx.z;
    const __half* __restrict__ B = args.B[z];
    float acc[2][8][4];
    GEMM_MAINLOOP(A, B, acc)

    const int quad = lane >> 2;
    const int qt = lane & 3;
    __half* O = args.O[z];
    #pragma unroll
    for (int mt = 0; mt < 2; mt++) {
        const int r_lo = row0 + mrow + mt * 16 + quad;
        #pragma unroll
        for (int nt = 0; nt < 8; nt++) {
            const int col = col0 + ncol + nt * 8 + 2 * qt;
            #pragma unroll
            for (int half = 0; half < 2; half++) {
                const size_t o = (size_t)(r_lo + 8 * half) * DD + col;
                *(uint32_t*)&O[o] =
                    pack_f16x2(acc[mt][nt][2 * half], acc[mt][nt][2 * half + 1]);
            }
        }
    }
}

// O-proj: f32 out + bias
__global__ __launch_bounds__(256) void gemm_1pf(
    const __half* __restrict__ A, const __half* __restrict__ Bw,
    const float* __restrict__ bias, float* __restrict__ C)
{
    extern __shared__ __align__(128) char smem[];
    const __half* __restrict__ B = Bw;
    float acc[2][8][4];
    GEMM_MAINLOOP(A, B, acc)

    const int quad = lane >> 2;
    const int qt = lane & 3;
    #pragma unroll
    for (int mt = 0; mt < 2; mt++) {
        const int r_lo = row0 + mrow + mt * 16 + quad;
        #pragma unroll
        for (int nt = 0; nt < 8; nt++) {
            const int col = col0 + ncol + nt * 8 + 2 * qt;
            float2 v0 = make_float2(acc[mt][nt][0], acc[mt][nt][1]);
            float2 v1 = make_float2(acc[mt][nt][2], acc[mt][nt][3]);
            const float2 bv = *(const float2*)&bias[col];
            v0.x += bv.x; v0.y += bv.y;
            v1.x += bv.x; v1.y += bv.y;
            *(float2*)&C[(size_t)r_lo * DD + col] = v0;
            *(float2*)&C[(size_t)(r_lo + 8) * DD + col] = v1;
        }
    }
}

// ---------------------------------------------------------------------------
// Tensor-core causal flash attention, diagonal-paired (each CTA: q-tile 31-i
// then q-tile i -> exactly 33 KV tiles per CTA; grid 512 = one wave).
// 3-stage KV ring buffer (depth-2 prefetch), one sync per tile.
// 64 q rows (4 warps x 16), XOR swizzle, 4 CTAs/SM (56KB smem).
// Q pre-scaled by CE2; P = ex2.f16x2; ones-MMA row sums.
// ---------------------------------------------------------------------------
#define AQ_BYTES (64 * 128)                  // 8192
#define AKV_MAT (64 * 128)                   // 8192
#define AKV_STG (2 * AKV_MAT)                // 16384
#define NST 3
#define ASMEM_BYTES (AQ_BYTES + NST * AKV_STG) // 57344
#define NQT (NN / 64)                        // 32 q-tiles per (b,h)

__global__ __launch_bounds__(128, 4) void attn_tc(
    const __half* __restrict__ Qe, const __half* __restrict__ Ke,
    const __half* __restrict__ Ve, __half* __restrict__ Ce)
{
    extern __shared__ __align__(128) char smem[];
    const uint32_t sb = smem_to_u32(smem);
    const int OFF_Q = 0, OFF_ST = AQ_BYTES;

    const int tid = threadIdx.x;
    const int wid = tid >> 5;
    const int lane = tid & 31;
    const int quad = lane >> 2;
    const int qt = lane & 3;
    const int lm = lane & 15;
    const int hc = (lane >> 4) & 1;

    const int pairi = blockIdx.x;     // 0..15
    const int h = blockIdx.y;
    const int b = blockIdx.z;
    const int hoff = h * DH;
    const int rowg = b * NN;

    #define LOADKV(kt, st) do { \
        _Pragma("unroll") \
        for (int i = 0; i < 8; i++) { \
            const int idx = tid + i * 128; \
            const int mat = idx >> 9; \
            const int r = (idx >> 3) & 63; \
            const int c = idx & 7; \
            const uint32_t dst = sb + OFF_ST + (st) * AKV_STG + mat * AKV_MAT \
                               + SW_OFF(r, c); \
            const size_t g = (size_t)(rowg + (kt) * 64 + r) * DD + hoff + c * 8; \
            CP_ASYNC16(dst, (mat ? Ve : Ke) + g); \
        } \
    } while (0)

    #pragma unroll 1
    for (int pass = 0; pass < 2; pass++) {
        const int qb = pass ? pairi : (NQT - 1 - pairi);
        const int q0 = qb * 64;
        const int nkt = qb + 1;

        // Prologue: group0 = Q + KV0 ; group1 = KV1 (if any)
        #pragma unroll
        for (int i = 0; i < 4; i++) {
            const int idx = tid + i * 128;
            const int r = idx >> 3, c = idx & 7;
            CP_ASYNC16(sb + OFF_Q + SW_OFF(r, c),
                       Qe + (size_t)(rowg + q0 + r) * DD + hoff + c * 8);
        }
        LOADKV(0, 0);
        CP_COMMIT();
        if (nkt > 1) {
            LOADKV(1, 1);
            CP_COMMIT();
            CP_WAIT(1);
        } else {
            CP_WAIT(0);
        }
        __syncthreads();

        uint32_t qf[4][4];
        #pragma unroll
        for (int kk = 0; kk < 4; kk++)
            LDSM4(qf[kk], sb + OFF_Q + SW_OFF(wid * 16 + lm, kk * 2 + hc));

        float ctx[8][4];
        #pragma unroll
        for (int j = 0; j < 8; j++)
            #pragma unroll
            for (int k = 0; k < 4; k++) ctx[j][k] = 0.f;
        float lacc[4] = {0.f, 0.f, 0.f, 0.f};

        const int rbase = q0 + wid * 16 + quad;
        const int wrow0 = q0 + wid * 16;

        int scur = 0;                 // stage holding tile kt
        for (int kt = 0; kt < nkt; kt++) {
            if (kt + 1 < nkt) CP_WAIT(1); else CP_WAIT(0);
            __syncthreads();          // publish kt's tile; prove write-stage free
            if (kt + 2 < nkt) {
                const int swr = (scur >= 1) ? (scur - 1) : 2;   // (scur+2)%3
                LOADKV(kt + 2, swr);
                CP_COMMIT();
            }

            const uint32_t sK = sb + OFF_ST + scur * AKV_STG;
            const uint32_t sV = sK + AKV_MAT;

            // ---- S = Q @ K^T (log2 units) ----
            float sacc[8][4];
            #pragma unroll
            for (int j = 0; j < 8; j++)
                #pragma unroll
                for (int k = 0; k < 4; k++) sacc[j][k] = 0.f;

            #pragma unroll
            for (int kk = 0; kk < 4; kk++) {
                uint32_t kf[4][4];
                #pragma unroll
                for (int nt = 0; nt < 4; nt++)
                    LDSM4(kf[nt], sK + SW_OFF(nt * 16 + lm, kk * 2 + hc));
                #pragma unroll
                for (int nt = 0; nt < 4; nt++) {
                    MMAF16(sacc[2 * nt + 0], qf[kk], kf[nt][0], kf[nt][2]);
                    MMAF16(sacc[2 * nt + 1], qf[kk], kf[nt][1], kf[nt][3]);
                }
            }

            // ---- causal mask (diagonal tiles only) ----
            if ((kt + 1) * 64 > wrow0) {
                const int kcb = kt * 64 + 2 * qt;
                #pragma unroll
                for (int j = 0; j < 8; j++) {
                    const int c0 = kcb + j * 8;
                    if (c0     > rbase    ) sacc[j][0] = -60000.f;
                    if (c0 + 1 > rbase    ) sacc[j][1] = -60000.f;
                    if (c0     > rbase + 8) sacc[j][2] = -60000.f;
                    if (c0 + 1 > rbase + 8) sacc[j][3] = -60000.f;
                }
            }

            // ---- P = ex2(S) in fp16x2; row sums via ones-MMA ----
            uint32_t pf[4][4];
            #pragma unroll
            for (int t = 0; t < 4; t++) {
                #pragma unroll
                for (int g = 0; g < 4; g++) {
                    const int jj = 2 * t + (g >> 1);
                    const int o = (g & 1) * 2;
                    pf[t][g] = h2ex2(pack_f16x2(sacc[jj][o + 0], sacc[jj][o + 1]));
                }
            }
            #pragma unroll
            for (int t = 0; t < 4; t++)
                MMAF16(lacc, pf[t], ONES2, ONES2);

            // ---- ctx += P @ V ----
            #pragma unroll
            for (int t = 0; t < 4; t++) {
                #pragma unroll
                for (int jj = 0; jj < 4; jj++) {
                    uint32_t vf[4];
                    LDSM4T(vf, sV + SW_OFF(t * 16 + lm, jj * 2 + hc));
                    MMAF16(ctx[2 * jj + 0], pf[t], vf[0], vf[1]);
                    MMAF16(ctx[2 * jj + 1], pf[t], vf[2], vf[3]);
                }
            }

            scur = (scur == 2) ? 0 : (scur + 1);
        }

        // ---- epilogue for this pass ----
        const float i0 = 1.f / lacc[0];
        const float i1 = 1.f / lacc[2];
        #pragma unroll
        for (int jj = 0; jj < 8; jj++) {
            const int col = hoff + jj * 8 + 2 * qt;
            #pragma unroll
            for (int half = 0; half < 2; half++) {
                const float inv = half ? i1 : i0;
                const size_t o = (size_t)(rowg + rbase + 8 * half) * DD + col;
                *(uint32_t*)&Ce[o] = pack_f16x2(ctx[jj][2 * half + 0] * inv,
                                                ctx[jj][2 * half + 1] * inv);
            }
        }
        __syncthreads();   // smem safe to reuse in next pass
    }
    #undef LOADKV
}

// ---------------------------------------------------------------------------
// Launch
// ---------------------------------------------------------------------------
extern "C" void kernel_launch(void* const* d_in, const int* in_sizes, int n_in,
                              void* d_out, int out_size)
{
    const float* x  = (const float*)d_in[0];
    const float* Wq = (const float*)d_in[1];
    const float* Wk = (const float*)d_in[2];
    const float* Wv = (const float*)d_in[3];
    const float* Wo = (const float*)d_in[4];
    const float* bo = (const float*)d_in[5];
    float* out = (float*)d_out;

    __half *xe, *Qe, *Ke, *Ve, *Ce;
    cudaGetSymbolAddress((void**)&xe, g_xe);
    cudaGetSymbolAddress((void**)&Qe, g_Qe);
    cudaGetSymbolAddress((void**)&Ke, g_Ke);
    cudaGetSymbolAddress((void**)&Ve, g_Ve);
    cudaGetSymbolAddress((void**)&Ce, g_Ce);
    __half *Wqt, *Wkt, *Wvt, *Wot;
    cudaGetSymbolAddress((void**)&Wqt, g_Wqt);
    cudaGetSymbolAddress((void**)&Wkt, g_Wkt);
    cudaGetSymbolAddress((void**)&Wvt, g_Wvt);
    cudaGetSymbolAddress((void**)&Wot, g_Wot);

    cudaFuncSetAttribute(gemm_1p, cudaFuncAttributeMaxDynamicSharedMemorySize, G1SMEM);
    cudaFuncSetAttribute(gemm_1pf, cudaFuncAttributeMaxDynamicSharedMemorySize, G1SMEM);
    cudaFuncSetAttribute(attn_tc, cudaFuncAttributeMaxDynamicSharedMemorySize, ASMEM_BYTES);

    // Fused prep: 4 weight transposes + x conversion in one launch
    {
        PrepArgs p;
        p.W[0] = Wq; p.Wt[0] = Wqt; p.scale[0] = CE2;
        p.W[1] = Wk; p.Wt[1] = Wkt; p.scale[1] = 1.f;
        p.W[2] = Wv; p.Wt[2] = Wvt; p.scale[2] = 1.f;
        p.W[3] = Wo; p.Wt[3] = Wot; p.scale[3] = 1.f;
        p.x = x; p.xe = xe;
        dim3 tb(32, 8), tg(DD / 32, DD / 32, 5);
        prep_all<<<tg, tb>>>(p);
    }

    // Fused QKV projections (single product)
    {
        Gemm1Args a;
        a.B[0] = Wqt; a.O[0] = Qe;
        a.B[1] = Wkt; a.O[1] = Ke;
        a.B[2] = Wvt; a.O[2] = Ve;
        dim3 gg(DD / 128, MTOT / 128, 3);
        gemm_1p<<<gg, 256, G1SMEM>>>(xe, a);
    }

    // Tensor-core attention: 512 CTAs, each = one heavy + one light q-tile
    {
        dim3 ga(NQT / 2, HH, BB);   // (16, 16, 2)
        attn_tc<<<ga, 128, ASMEM_BYTES>>>(Qe, Ke, Ve, Ce);
    }

    // Output projection (single product, f32 + bias)
    {
        dim3 gg(DD / 128, MTOT / 128);
        gemm_1pf<<<gg, 256, G1SMEM>>>(Ce, Wot, bo, out);
    }
}